// round 14
// baseline (speedup 1.0000x reference)
#include <cuda_runtime.h>
#include <cuda_fp16.h>
#include <math.h>

// ---------------------------------------------------------------------------
// out[e] = sigmoid( relu(x_e @ W1 + b1) @ W2 + b2 ),
// x_e = [h[src], rel_table[type], rel_table[q], time_table[time]]
//
// Decomposed into per-node / per-rel / per-time 128x128 projections (fp16,
// HMMA). Query projection + b1 folded into rel rows. Edge pass: one warp per
// edge-pair (16 lanes/edge), two-level register pipeline: indices prefetched
// 2 iters ahead, node rows (the L2-latency gathers) 1 iter ahead; rel/time
// rows are L1-resident direct loads.
// ---------------------------------------------------------------------------

#define D 128
#define MAX_NODES 100000
#define MAX_RELS  500
#define MAX_TIMES 1000

__device__ __align__(128) __half g_node_proj[(size_t)MAX_NODES * D];
__device__ __align__(128) __half g_rel_proj[(size_t)MAX_RELS * D];   // + rq@W1c + b1
__device__ __align__(128) __half g_time_proj[(size_t)MAX_TIMES * D];
__device__ __align__(16)  __half g_w2h[D];

// ---- mma / ldmatrix helpers ------------------------------------------------
__device__ __forceinline__ unsigned smem_u32(const void* p) {
    return (unsigned)__cvta_generic_to_shared(p);
}
__device__ __forceinline__ void ldm_x4(unsigned* r, unsigned addr) {
    asm volatile("ldmatrix.sync.aligned.m8n8.x4.shared.b16 {%0,%1,%2,%3}, [%4];"
                 : "=r"(r[0]), "=r"(r[1]), "=r"(r[2]), "=r"(r[3]) : "r"(addr));
}
__device__ __forceinline__ void ldm_x4_trans(unsigned* r, unsigned addr) {
    asm volatile("ldmatrix.sync.aligned.m8n8.x4.trans.shared.b16 {%0,%1,%2,%3}, [%4];"
                 : "=r"(r[0]), "=r"(r[1]), "=r"(r[2]), "=r"(r[3]) : "r"(addr));
}
__device__ __forceinline__ void mma_16816(float* c, const unsigned* a,
                                          const unsigned* b) {
    asm volatile(
        "mma.sync.aligned.m16n8k16.row.col.f32.f16.f16.f32 "
        "{%0,%1,%2,%3}, {%4,%5,%6,%7}, {%8,%9}, {%0,%1,%2,%3};"
        : "+f"(c[0]), "+f"(c[1]), "+f"(c[2]), "+f"(c[3])
        : "r"(a[0]), "r"(a[1]), "r"(a[2]), "r"(a[3]), "r"(b[0]), "r"(b[1]));
}

#define BM 128
#define KC 64

// ---------------------------------------------------------------------------
// Fused prep kernel (R11 form — best measured): 128x128 tile per block,
// K=128 in two KC=64 steps. 8 warps; warp w owns rows (w&3)*32, cols (w>>2)*64.
// ---------------------------------------------------------------------------
__global__ __launch_bounds__(256) void prep_kernel(
    const float* __restrict__ h,
    const float* __restrict__ rel_table,
    const float* __restrict__ time_table,
    const float* __restrict__ W1,
    const float* __restrict__ b1,
    const float* __restrict__ W2,
    const int* __restrict__ qptr,
    int n_nodes, int n_rels, int n_times)
{
    __shared__ __align__(16) __half As[128][72];
    __shared__ __align__(16) __half Bs[64][136];
    __shared__ float cbias_s[D];
    __shared__ float rq_s[D];

    const int tid  = threadIdx.x;
    const int lane = tid & 31;
    const int w    = tid >> 5;
    const int warp_m = (w & 3) * 32;
    const int warp_n = (w >> 2) * 64;

    const int nb_node = (n_nodes + BM - 1) / BM;
    const int nb_rel  = (n_rels  + BM - 1) / BM;

    if (blockIdx.x == 0 && tid < D)
        g_w2h[tid] = __float2half(__ldg(W2 + tid));
    if (tid < D) cbias_s[tid] = 0.f;

    const float* A;
    __half* C;
    int w_off, M, m0;
    bool is_rel = false;

    int bx = blockIdx.x;
    if (bx < nb_node) {
        A = h; C = g_node_proj; w_off = 0; M = n_nodes; m0 = bx * BM;
    } else if (bx < nb_node + nb_rel) {
        A = rel_table; C = g_rel_proj; w_off = 128; M = n_rels;
        m0 = (bx - nb_node) * BM; is_rel = true;
    } else {
        A = time_table; C = g_time_proj; w_off = 384; M = n_times;
        m0 = (bx - nb_node - nb_rel) * BM;
    }

    if (is_rel && tid < D) {
        int q = qptr[0];
        rq_s[tid] = __ldg(rel_table + (size_t)q * D + tid);
    }

    float acc[2][8][4];
#pragma unroll
    for (int mi = 0; mi < 2; mi++)
#pragma unroll
        for (int ni = 0; ni < 8; ni++)
#pragma unroll
            for (int c = 0; c < 4; c++) acc[mi][ni][c] = 0.f;

    for (int k0 = 0; k0 < D; k0 += KC) {
        __syncthreads();
#pragma unroll
        for (int it = 0; it < 8; it++) {
            int i   = tid + it * 256;
            int row = i >> 4;
            int c4  = i & 15;
            float4 v = make_float4(0.f, 0.f, 0.f, 0.f);
            int grow = m0 + row;
            if (grow < M)
                v = *(const float4*)(A + (size_t)grow * D + k0 + c4 * 4);
            __half2 h01 = __floats2half2_rn(v.x, v.y);
            __half2 h23 = __floats2half2_rn(v.z, v.w);
            uint2 pv;
            pv.x = *(unsigned*)&h01; pv.y = *(unsigned*)&h23;
            *(uint2*)(&As[row][c4 * 4]) = pv;
        }
#pragma unroll
        for (int it = 0; it < 8; it++) {
            int i   = tid + it * 256;
            int kk  = i >> 5;
            int c4  = i & 31;
            float4 v = *(const float4*)(W1 + (size_t)(w_off + k0 + kk) * D + c4 * 4);
            __half2 h01 = __floats2half2_rn(v.x, v.y);
            __half2 h23 = __floats2half2_rn(v.z, v.w);
            uint2 pv;
            pv.x = *(unsigned*)&h01; pv.y = *(unsigned*)&h23;
            *(uint2*)(&Bs[kk][c4 * 4]) = pv;
        }
        __syncthreads();

#pragma unroll
        for (int ks = 0; ks < KC / 16; ks++) {
            unsigned a[2][4];
            {
                int arow = (lane & 7) + ((lane >> 3) & 1) * 8;
                int acol = ks * 16 + (lane >> 4) * 8;
#pragma unroll
                for (int mi = 0; mi < 2; mi++)
                    ldm_x4(a[mi], smem_u32(&As[warp_m + mi * 16 + arow][acol]));
            }
            unsigned b[8][2];
            {
                int krow = ks * 16 + (lane & 7) + ((lane >> 3) & 1) * 8;
#pragma unroll
                for (int p = 0; p < 4; p++) {
                    unsigned r[4];
                    int ncol = warp_n + p * 16 + (lane >> 4) * 8;
                    ldm_x4_trans(r, smem_u32(&Bs[krow][ncol]));
                    b[2 * p][0]     = r[0]; b[2 * p][1]     = r[1];
                    b[2 * p + 1][0] = r[2]; b[2 * p + 1][1] = r[3];
                }
            }
#pragma unroll
            for (int mi = 0; mi < 2; mi++)
#pragma unroll
                for (int ni = 0; ni < 8; ni++)
                    mma_16816(acc[mi][ni], a[mi], b[ni]);
        }
    }

    if (is_rel) {
        if (tid < D) {
            int j = tid;
            float s = __ldg(b1 + j);
            const float* Wc = W1 + (size_t)256 * D + j;
#pragma unroll 8
            for (int k = 0; k < D; k++)
                s += rq_s[k] * __ldg(Wc + (size_t)k * D);
            cbias_s[j] = s;
        }
        __syncthreads();
    }

    const int erow = lane >> 2;
    const int ecol = (lane & 3) * 2;
#pragma unroll
    for (int mi = 0; mi < 2; mi++) {
#pragma unroll
        for (int ni = 0; ni < 8; ni++) {
            int col = warp_n + ni * 8 + ecol;
            float cb0 = cbias_s[col], cb1 = cbias_s[col + 1];
            int r0 = m0 + warp_m + mi * 16 + erow;
            if (r0 < M) {
                __half2 v = __floats2half2_rn(acc[mi][ni][0] + cb0,
                                              acc[mi][ni][1] + cb1);
                *(__half2*)(C + (size_t)r0 * D + col) = v;
            }
            int r1 = r0 + 8;
            if (r1 < M) {
                __half2 v = __floats2half2_rn(acc[mi][ni][2] + cb0,
                                              acc[mi][ni][3] + cb1);
                *(__half2*)(C + (size_t)r1 * D + col) = v;
            }
        }
    }
}

// ---------------------------------------------------------------------------
// Edge pass: one warp per pair of edges. Lanes 0-15 -> edge 2p, lanes 16-31
// -> edge 2p+1; lane covers features [8*sl, 8*sl+8) (one uint4 per table).
// Pipeline: indices prefetched 2 iters ahead, node rows 1 iter ahead.
// ---------------------------------------------------------------------------
__device__ __forceinline__ float edge_partial(uint4 av, uint4 bv, uint4 cv,
                                              uint4 wv)
{
    const __half2 z2 = __float2half2_rn(0.f);
    __half2 acc;
    {
        __half2 x = __hmax2(__hadd2(__hadd2(*(__half2*)&av.x, *(__half2*)&bv.x),
                                    *(__half2*)&cv.x), z2);
        acc = __hmul2(x, *(__half2*)&wv.x);
    }
    {
        __half2 x = __hmax2(__hadd2(__hadd2(*(__half2*)&av.y, *(__half2*)&bv.y),
                                    *(__half2*)&cv.y), z2);
        acc = __hfma2(x, *(__half2*)&wv.y, acc);
    }
    {
        __half2 x = __hmax2(__hadd2(__hadd2(*(__half2*)&av.z, *(__half2*)&bv.z),
                                    *(__half2*)&cv.z), z2);
        acc = __hfma2(x, *(__half2*)&wv.z, acc);
    }
    {
        __half2 x = __hmax2(__hadd2(__hadd2(*(__half2*)&av.w, *(__half2*)&bv.w),
                                    *(__half2*)&cv.w), z2);
        acc = __hfma2(x, *(__half2*)&wv.w, acc);
    }
    float2 f = __half22float2(acc);
    return f.x + f.y;
}

__global__ __launch_bounds__(256, 5) void edge_kernel(
    const int* __restrict__ edge_src,
    const int* __restrict__ edge_type,
    const int* __restrict__ edge_time,
    const float* __restrict__ b2,
    float* __restrict__ out, int E)
{
    const int lane = threadIdx.x & 31;
    const int sl   = lane & 15;          // feature slot within edge
    const int half = lane >> 4;          // 0 = edge A, 1 = edge B
    const int gw   = (int)(blockIdx.x * 8u + (threadIdx.x >> 5));
    const int nw   = (int)(gridDim.x * 8u);

    const uint4* __restrict__ np = (const uint4*)g_node_proj;
    const uint4* __restrict__ rp = (const uint4*)g_rel_proj;
    const uint4* __restrict__ tp = (const uint4*)g_time_proj;

    const uint4 wv  = __ldg((const uint4*)g_w2h + sl);
    const float b2v = __ldg(b2);
    const int npair = E >> 1;

    // --- pipeline state ---
    int p0 = gw;                 // compute iter
    int p1 = p0 + nw;            // node-prefetch iter
    int p2 = p1 + nw;            // idx-prefetch iter

    int2 s0 = make_int2(0, 0), r0 = s0, t0 = s0;
    int2 s1 = s0, r1 = s0, t1 = s0;
    uint4 n0 = make_uint4(0, 0, 0, 0);

    if (p0 < npair) {
        s0 = __ldg((const int2*)edge_src  + p0);
        r0 = __ldg((const int2*)edge_type + p0);
        t0 = __ldg((const int2*)edge_time + p0);
        n0 = np[(size_t)(half ? s0.y : s0.x) * 16 + sl];
    }
    if (p1 < npair) {
        s1 = __ldg((const int2*)edge_src  + p1);
        r1 = __ldg((const int2*)edge_type + p1);
        t1 = __ldg((const int2*)edge_time + p1);
    }

    while (p0 < npair) {
        // Level-2 prefetch: indices for p2.
        int2 s2 = make_int2(0, 0), r2 = s2, t2 = s2;
        if (p2 < npair) {
            s2 = __ldg((const int2*)edge_src  + p2);
            r2 = __ldg((const int2*)edge_type + p2);
            t2 = __ldg((const int2*)edge_time + p2);
        }
        // Level-1 prefetch: node row for p1 (safe: s1 zeroed when OOB).
        uint4 n1 = np[(size_t)(half ? s1.y : s1.x) * 16 + sl];

        // Compute current pair: rel/time are L1-resident direct loads.
        uint4 bv = rp[(size_t)(half ? r0.y : r0.x) * 16 + sl];
        uint4 cv = tp[(size_t)(half ? t0.y : t0.x) * 16 + sl];

        float d = edge_partial(n0, bv, cv, wv);
#pragma unroll
        for (int off = 8; off; off >>= 1)
            d += __shfl_xor_sync(0xffffffffu, d, off);
        // lane 0 holds dA, lane 16 holds dB.
        float dB = __shfl_sync(0xffffffffu, d, 16);
        if (lane == 0) {
            float2 o;
            o.x = 1.f / (1.f + __expf(-(d  + b2v)));
            o.y = 1.f / (1.f + __expf(-(dB + b2v)));
            *(float2*)(out + (size_t)p0 * 2) = o;
        }

        // Rotate pipeline.
        p0 = p1; p1 = p2; p2 += nw;
        s0 = s1; r0 = r1; t0 = t1;
        s1 = s2; r1 = r2; t1 = t2;
        n0 = n1;
    }

    // Odd tail edge handled by warp 0 (all lanes compute edge E-1; lanes
    // 16-31 duplicate lanes 0-15, reduction over 16 lanes is unaffected).
    if ((E & 1) && gw == 0) {
        int e = E - 1;
        int se = __ldg(edge_src + e);
        int re = __ldg(edge_type + e);
        int te = __ldg(edge_time + e);
        uint4 av = np[(size_t)se * 16 + sl];
        uint4 bv = rp[(size_t)re * 16 + sl];
        uint4 cv = tp[(size_t)te * 16 + sl];
        float d = edge_partial(av, bv, cv, wv);
#pragma unroll
        for (int off = 8; off; off >>= 1)
            d += __shfl_xor_sync(0xffffffffu, d, off);
        if (lane == 0)
            out[e] = 1.f / (1.f + __expf(-(d + b2v)));
    }
}

// ---------------------------------------------------------------------------
extern "C" void kernel_launch(void* const* d_in, const int* in_sizes, int n_in,
                              void* d_out, int out_size)
{
    const float* h          = (const float*)d_in[0];
    const int*   edge_index = (const int*)d_in[1];
    const int*   edge_type  = (const int*)d_in[2];
    const int*   edge_time  = (const int*)d_in[3];
    const int*   query_rel  = (const int*)d_in[4];
    const float* rel_table  = (const float*)d_in[5];
    const float* time_table = (const float*)d_in[6];
    const float* W1         = (const float*)d_in[7];
    const float* b1         = (const float*)d_in[8];
    const float* W2         = (const float*)d_in[9];
    const float* b2         = (const float*)d_in[10];
    float*       out        = (float*)d_out;

    const int n_nodes = in_sizes[0] / D;
    const int n_rels  = in_sizes[5] / D;
    const int n_times = in_sizes[6] / D;
    const int E       = in_sizes[2];

    const int nb_node = (n_nodes + BM - 1) / BM;
    const int nb_rel  = (n_rels  + BM - 1) / BM;
    const int nb_time = (n_times + BM - 1) / BM;

    prep_kernel<<<nb_node + nb_rel + nb_time, 256>>>(
        h, rel_table, time_table, W1, b1, W2, query_rel,
        n_nodes, n_rels, n_times);

    // One warp per edge-pair, grid-stride: 2048 blocks x 8 warps.
    edge_kernel<<<2048, 256>>>(edge_index, edge_type, edge_time, b2, out, E);
}

// round 15
// speedup vs baseline: 1.2855x; 1.2855x over previous
#include <cuda_runtime.h>
#include <cuda_fp16.h>
#include <math.h>

// ---------------------------------------------------------------------------
// out[e] = sigmoid( relu(x_e @ W1 + b1) @ W2 + b2 ),
// x_e = [h[src], rel_table[type], rel_table[q], time_table[time]]
//
// Decomposed into per-node / per-rel / per-time 128x128 projections (fp16),
// computed with HMMA tensor cores. Query projection + b1 folded into rel
// rows. Edge pass (R11 form): 8 lanes/edge, 2 edges per group-iter, index
// loads software-pipelined; node gathers use L1::no_allocate so the hot
// rel/time tables stay L1-resident.
// ---------------------------------------------------------------------------

#define D 128
#define MAX_NODES 100000
#define MAX_RELS  500
#define MAX_TIMES 1000

__device__ __align__(128) __half g_node_proj[(size_t)MAX_NODES * D];
__device__ __align__(128) __half g_rel_proj[(size_t)MAX_RELS * D];   // + rq@W1c + b1
__device__ __align__(128) __half g_time_proj[(size_t)MAX_TIMES * D];
__device__ __align__(16)  __half g_w2h[D];

// ---- mma / ldmatrix helpers ------------------------------------------------
__device__ __forceinline__ unsigned smem_u32(const void* p) {
    return (unsigned)__cvta_generic_to_shared(p);
}
__device__ __forceinline__ void ldm_x4(unsigned* r, unsigned addr) {
    asm volatile("ldmatrix.sync.aligned.m8n8.x4.shared.b16 {%0,%1,%2,%3}, [%4];"
                 : "=r"(r[0]), "=r"(r[1]), "=r"(r[2]), "=r"(r[3]) : "r"(addr));
}
__device__ __forceinline__ void ldm_x4_trans(unsigned* r, unsigned addr) {
    asm volatile("ldmatrix.sync.aligned.m8n8.x4.trans.shared.b16 {%0,%1,%2,%3}, [%4];"
                 : "=r"(r[0]), "=r"(r[1]), "=r"(r[2]), "=r"(r[3]) : "r"(addr));
}
__device__ __forceinline__ void mma_16816(float* c, const unsigned* a,
                                          const unsigned* b) {
    asm volatile(
        "mma.sync.aligned.m16n8k16.row.col.f32.f16.f16.f32 "
        "{%0,%1,%2,%3}, {%4,%5,%6,%7}, {%8,%9}, {%0,%1,%2,%3};"
        : "+f"(c[0]), "+f"(c[1]), "+f"(c[2]), "+f"(c[3])
        : "r"(a[0]), "r"(a[1]), "r"(a[2]), "r"(a[3]), "r"(b[0]), "r"(b[1]));
}

// Streaming gather: bypass L1 allocation (keeps rel/time tables resident).
__device__ __forceinline__ uint4 ldg_na(const uint4* p) {
    uint4 v;
    asm volatile("ld.global.nc.L1::no_allocate.v4.u32 {%0,%1,%2,%3}, [%4];"
                 : "=r"(v.x), "=r"(v.y), "=r"(v.z), "=r"(v.w) : "l"(p));
    return v;
}

#define BM 128
#define KC 64

// ---------------------------------------------------------------------------
// Fused prep kernel (R11 form — best measured): 128x128 tile per block,
// K=128 in two KC=64 steps. 8 warps; warp w owns rows (w&3)*32, cols (w>>2)*64.
// ---------------------------------------------------------------------------
__global__ __launch_bounds__(256) void prep_kernel(
    const float* __restrict__ h,
    const float* __restrict__ rel_table,
    const float* __restrict__ time_table,
    const float* __restrict__ W1,
    const float* __restrict__ b1,
    const float* __restrict__ W2,
    const int* __restrict__ qptr,
    int n_nodes, int n_rels, int n_times)
{
    __shared__ __align__(16) __half As[128][72];
    __shared__ __align__(16) __half Bs[64][136];
    __shared__ float cbias_s[D];
    __shared__ float rq_s[D];

    const int tid  = threadIdx.x;
    const int lane = tid & 31;
    const int w    = tid >> 5;
    const int warp_m = (w & 3) * 32;
    const int warp_n = (w >> 2) * 64;

    const int nb_node = (n_nodes + BM - 1) / BM;
    const int nb_rel  = (n_rels  + BM - 1) / BM;

    if (blockIdx.x == 0 && tid < D)
        g_w2h[tid] = __float2half(__ldg(W2 + tid));
    if (tid < D) cbias_s[tid] = 0.f;

    const float* A;
    __half* C;
    int w_off, M, m0;
    bool is_rel = false;

    int bx = blockIdx.x;
    if (bx < nb_node) {
        A = h; C = g_node_proj; w_off = 0; M = n_nodes; m0 = bx * BM;
    } else if (bx < nb_node + nb_rel) {
        A = rel_table; C = g_rel_proj; w_off = 128; M = n_rels;
        m0 = (bx - nb_node) * BM; is_rel = true;
    } else {
        A = time_table; C = g_time_proj; w_off = 384; M = n_times;
        m0 = (bx - nb_node - nb_rel) * BM;
    }

    if (is_rel && tid < D) {
        int q = qptr[0];
        rq_s[tid] = __ldg(rel_table + (size_t)q * D + tid);
    }

    float acc[2][8][4];
#pragma unroll
    for (int mi = 0; mi < 2; mi++)
#pragma unroll
        for (int ni = 0; ni < 8; ni++)
#pragma unroll
            for (int c = 0; c < 4; c++) acc[mi][ni][c] = 0.f;

    for (int k0 = 0; k0 < D; k0 += KC) {
        __syncthreads();
#pragma unroll
        for (int it = 0; it < 8; it++) {
            int i   = tid + it * 256;
            int row = i >> 4;
            int c4  = i & 15;
            float4 v = make_float4(0.f, 0.f, 0.f, 0.f);
            int grow = m0 + row;
            if (grow < M)
                v = *(const float4*)(A + (size_t)grow * D + k0 + c4 * 4);
            __half2 h01 = __floats2half2_rn(v.x, v.y);
            __half2 h23 = __floats2half2_rn(v.z, v.w);
            uint2 pv;
            pv.x = *(unsigned*)&h01; pv.y = *(unsigned*)&h23;
            *(uint2*)(&As[row][c4 * 4]) = pv;
        }
#pragma unroll
        for (int it = 0; it < 8; it++) {
            int i   = tid + it * 256;
            int kk  = i >> 5;
            int c4  = i & 31;
            float4 v = *(const float4*)(W1 + (size_t)(w_off + k0 + kk) * D + c4 * 4);
            __half2 h01 = __floats2half2_rn(v.x, v.y);
            __half2 h23 = __floats2half2_rn(v.z, v.w);
            uint2 pv;
            pv.x = *(unsigned*)&h01; pv.y = *(unsigned*)&h23;
            *(uint2*)(&Bs[kk][c4 * 4]) = pv;
        }
        __syncthreads();

#pragma unroll
        for (int ks = 0; ks < KC / 16; ks++) {
            unsigned a[2][4];
            {
                int arow = (lane & 7) + ((lane >> 3) & 1) * 8;
                int acol = ks * 16 + (lane >> 4) * 8;
#pragma unroll
                for (int mi = 0; mi < 2; mi++)
                    ldm_x4(a[mi], smem_u32(&As[warp_m + mi * 16 + arow][acol]));
            }
            unsigned b[8][2];
            {
                int krow = ks * 16 + (lane & 7) + ((lane >> 3) & 1) * 8;
#pragma unroll
                for (int p = 0; p < 4; p++) {
                    unsigned r[4];
                    int ncol = warp_n + p * 16 + (lane >> 4) * 8;
                    ldm_x4_trans(r, smem_u32(&Bs[krow][ncol]));
                    b[2 * p][0]     = r[0]; b[2 * p][1]     = r[1];
                    b[2 * p + 1][0] = r[2]; b[2 * p + 1][1] = r[3];
                }
            }
#pragma unroll
            for (int mi = 0; mi < 2; mi++)
#pragma unroll
                for (int ni = 0; ni < 8; ni++)
                    mma_16816(acc[mi][ni], a[mi], b[ni]);
        }
    }

    if (is_rel) {
        if (tid < D) {
            int j = tid;
            float s = __ldg(b1 + j);
            const float* Wc = W1 + (size_t)256 * D + j;
#pragma unroll 8
            for (int k = 0; k < D; k++)
                s += rq_s[k] * __ldg(Wc + (size_t)k * D);
            cbias_s[j] = s;
        }
        __syncthreads();
    }

    const int erow = lane >> 2;
    const int ecol = (lane & 3) * 2;
#pragma unroll
    for (int mi = 0; mi < 2; mi++) {
#pragma unroll
        for (int ni = 0; ni < 8; ni++) {
            int col = warp_n + ni * 8 + ecol;
            float cb0 = cbias_s[col], cb1 = cbias_s[col + 1];
            int r0 = m0 + warp_m + mi * 16 + erow;
            if (r0 < M) {
                __half2 v = __floats2half2_rn(acc[mi][ni][0] + cb0,
                                              acc[mi][ni][1] + cb1);
                *(__half2*)(C + (size_t)r0 * D + col) = v;
            }
            int r1 = r0 + 8;
            if (r1 < M) {
                __half2 v = __floats2half2_rn(acc[mi][ni][2] + cb0,
                                              acc[mi][ni][3] + cb1);
                *(__half2*)(C + (size_t)r1 * D + col) = v;
            }
        }
    }
}

// ---------------------------------------------------------------------------
// Edge pass (R11 form): 8 lanes/edge, lane l covers uint4 slots {l, l+8}.
// Index loads prefetched one iteration ahead. Node gathers bypass L1.
// ---------------------------------------------------------------------------
__device__ __forceinline__ float edge_partial(uint4 av, uint4 bv, uint4 cv,
                                              uint4 wv)
{
    const __half2 z2 = __float2half2_rn(0.f);
    __half2 acc;
    {
        __half2 x = __hmax2(__hadd2(__hadd2(*(__half2*)&av.x, *(__half2*)&bv.x),
                                    *(__half2*)&cv.x), z2);
        acc = __hmul2(x, *(__half2*)&wv.x);
    }
    {
        __half2 x = __hmax2(__hadd2(__hadd2(*(__half2*)&av.y, *(__half2*)&bv.y),
                                    *(__half2*)&cv.y), z2);
        acc = __hfma2(x, *(__half2*)&wv.y, acc);
    }
    {
        __half2 x = __hmax2(__hadd2(__hadd2(*(__half2*)&av.z, *(__half2*)&bv.z),
                                    *(__half2*)&cv.z), z2);
        acc = __hfma2(x, *(__half2*)&wv.z, acc);
    }
    {
        __half2 x = __hmax2(__hadd2(__hadd2(*(__half2*)&av.w, *(__half2*)&bv.w),
                                    *(__half2*)&cv.w), z2);
        acc = __hfma2(x, *(__half2*)&wv.w, acc);
    }
    float2 f = __half22float2(acc);
    return f.x + f.y;
}

__global__ __launch_bounds__(256, 5) void edge_kernel(
    const int* __restrict__ edge_src,
    const int* __restrict__ edge_type,
    const int* __restrict__ edge_time,
    const float* __restrict__ b2,
    float* __restrict__ out, int E)
{
    __shared__ __align__(16) uint4 w2_s[16];

    const int l = threadIdx.x & 7;                          // lane in 8-group
    const int group  = (int)((blockIdx.x * 256u + threadIdx.x) >> 3);
    const int ngroup = (int)(gridDim.x * 256u / 8u);

    if (threadIdx.x < 16)
        w2_s[threadIdx.x] = ((const uint4*)g_w2h)[threadIdx.x];
    __syncthreads();

    const uint4* __restrict__ np = (const uint4*)g_node_proj;
    const uint4* __restrict__ rp = (const uint4*)g_rel_proj;
    const uint4* __restrict__ tp = (const uint4*)g_time_proj;

    const float b2v = __ldg(b2);
    const uint4 wv0 = w2_s[l];
    const uint4 wv1 = w2_s[l + 8];

    const int npair = E >> 1;

    // Prologue: prefetch first iteration's indices.
    int p = group;
    int2 s, r, t;
    if (p < npair) {
        s = __ldg((const int2*)edge_src  + p);
        r = __ldg((const int2*)edge_type + p);
        t = __ldg((const int2*)edge_time + p);
    }

    while (p < npair) {
        const int pn = p + ngroup;
        int2 sn, rn, tn;
        if (pn < npair) {                       // prefetch next iteration
            sn = __ldg((const int2*)edge_src  + pn);
            rn = __ldg((const int2*)edge_type + pn);
            tn = __ldg((const int2*)edge_time + pn);
        }

        // Block-strided slots: l (line 0) and l+8 (line 1).
        size_t o0 = (size_t)l;
        size_t o1 = (size_t)l + 8;
        // Node gathers: stream, don't allocate in L1.
        uint4 avA0 = ldg_na(np + (size_t)s.x * 16 + o0);
        uint4 avA1 = ldg_na(np + (size_t)s.x * 16 + o1);
        uint4 avB0 = ldg_na(np + (size_t)s.y * 16 + o0);
        uint4 avB1 = ldg_na(np + (size_t)s.y * 16 + o1);
        // Rel/time: hot tables, normal L1-allocating loads.
        uint4 bvA0 = rp[(size_t)r.x * 16 + o0], bvA1 = rp[(size_t)r.x * 16 + o1];
        uint4 cvA0 = tp[(size_t)t.x * 16 + o0], cvA1 = tp[(size_t)t.x * 16 + o1];
        uint4 bvB0 = rp[(size_t)r.y * 16 + o0], bvB1 = rp[(size_t)r.y * 16 + o1];
        uint4 cvB0 = tp[(size_t)t.y * 16 + o0], cvB1 = tp[(size_t)t.y * 16 + o1];

        float dA = edge_partial(avA0, bvA0, cvA0, wv0)
                 + edge_partial(avA1, bvA1, cvA1, wv1);
        float dB = edge_partial(avB0, bvB0, cvB0, wv0)
                 + edge_partial(avB1, bvB1, cvB1, wv1);

#pragma unroll
        for (int off = 4; off; off >>= 1) {
            dA += __shfl_xor_sync(0xffffffffu, dA, off);
            dB += __shfl_xor_sync(0xffffffffu, dB, off);
        }

        if (l == 0) {
            out[p * 2]     = 1.f / (1.f + __expf(-(dA + b2v)));
            out[p * 2 + 1] = 1.f / (1.f + __expf(-(dB + b2v)));
        }

        p = pn; s = sn; r = rn; t = tn;
    }

    // Odd tail edge handled by group 0.
    if ((E & 1) && group == 0) {
        int e = E - 1;
        int se = __ldg(edge_src + e);
        int re = __ldg(edge_type + e);
        int te = __ldg(edge_time + e);
        size_t o0 = (size_t)l;
        size_t o1 = (size_t)l + 8;
        float d = edge_partial(ldg_na(np + (size_t)se * 16 + o0),
                               rp[(size_t)re * 16 + o0],
                               tp[(size_t)te * 16 + o0], wv0)
                + edge_partial(ldg_na(np + (size_t)se * 16 + o1),
                               rp[(size_t)re * 16 + o1],
                               tp[(size_t)te * 16 + o1], wv1);
#pragma unroll
        for (int off = 4; off; off >>= 1)
            d += __shfl_xor_sync(0xffffffffu, d, off);
        if (l == 0)
            out[e] = 1.f / (1.f + __expf(-(d + b2v)));
    }
}

// ---------------------------------------------------------------------------
extern "C" void kernel_launch(void* const* d_in, const int* in_sizes, int n_in,
                              void* d_out, int out_size)
{
    const float* h          = (const float*)d_in[0];
    const int*   edge_index = (const int*)d_in[1];
    const int*   edge_type  = (const int*)d_in[2];
    const int*   edge_time  = (const int*)d_in[3];
    const int*   query_rel  = (const int*)d_in[4];
    const float* rel_table  = (const float*)d_in[5];
    const float* time_table = (const float*)d_in[6];
    const float* W1         = (const float*)d_in[7];
    const float* b1         = (const float*)d_in[8];
    const float* W2         = (const float*)d_in[9];
    const float* b2         = (const float*)d_in[10];
    float*       out        = (float*)d_out;

    const int n_nodes = in_sizes[0] / D;
    const int n_rels  = in_sizes[5] / D;
    const int n_times = in_sizes[6] / D;
    const int E       = in_sizes[2];

    const int nb_node = (n_nodes + BM - 1) / BM;
    const int nb_rel  = (n_rels  + BM - 1) / BM;
    const int nb_time = (n_times + BM - 1) / BM;

    prep_kernel<<<nb_node + nb_rel + nb_time, 256>>>(
        h, rel_table, time_table, W1, b1, W2, query_rel,
        n_nodes, n_rels, n_times);

    edge_kernel<<<2048, 256>>>(edge_index, edge_type, edge_time, b2, out, E);
}

// round 16
// speedup vs baseline: 1.3320x; 1.0362x over previous
#include <cuda_runtime.h>
#include <cuda_fp16.h>
#include <math.h>

// ---------------------------------------------------------------------------
// out[e] = sigmoid( relu(x_e @ W1 + b1) @ W2 + b2 ),
// x_e = [h[src], rel_table[type], rel_table[q], time_table[time]]
//
// Decomposed into per-node / per-rel / per-time 128x128 projections (fp16),
// computed with HMMA tensor cores in ONE K=128 chunk (single sync round,
// maximal load MLP). Query projection + b1 folded into rel rows.
// Edge pass: exact R11 form (best measured): 8 lanes/edge, 2 edges per
// group-iter, index loads software-pipelined one iteration ahead.
// ---------------------------------------------------------------------------

#define D 128
#define MAX_NODES 100000
#define MAX_RELS  500
#define MAX_TIMES 1000

__device__ __align__(128) __half g_node_proj[(size_t)MAX_NODES * D];
__device__ __align__(128) __half g_rel_proj[(size_t)MAX_RELS * D];   // + rq@W1c + b1
__device__ __align__(128) __half g_time_proj[(size_t)MAX_TIMES * D];
__device__ __align__(16)  __half g_w2h[D];

// ---- mma / ldmatrix helpers ------------------------------------------------
__device__ __forceinline__ unsigned smem_u32(const void* p) {
    return (unsigned)__cvta_generic_to_shared(p);
}
__device__ __forceinline__ void ldm_x4(unsigned* r, unsigned addr) {
    asm volatile("ldmatrix.sync.aligned.m8n8.x4.shared.b16 {%0,%1,%2,%3}, [%4];"
                 : "=r"(r[0]), "=r"(r[1]), "=r"(r[2]), "=r"(r[3]) : "r"(addr));
}
__device__ __forceinline__ void ldm_x4_trans(unsigned* r, unsigned addr) {
    asm volatile("ldmatrix.sync.aligned.m8n8.x4.trans.shared.b16 {%0,%1,%2,%3}, [%4];"
                 : "=r"(r[0]), "=r"(r[1]), "=r"(r[2]), "=r"(r[3]) : "r"(addr));
}
__device__ __forceinline__ void mma_16816(float* c, const unsigned* a,
                                          const unsigned* b) {
    asm volatile(
        "mma.sync.aligned.m16n8k16.row.col.f32.f16.f16.f32 "
        "{%0,%1,%2,%3}, {%4,%5,%6,%7}, {%8,%9}, {%0,%1,%2,%3};"
        : "+f"(c[0]), "+f"(c[1]), "+f"(c[2]), "+f"(c[3])
        : "r"(a[0]), "r"(a[1]), "r"(a[2]), "r"(a[3]), "r"(b[0]), "r"(b[1]));
}

#define BM 128

// ---------------------------------------------------------------------------
// Fused prep kernel: 128x128 output tile per block, K=128 in ONE chunk.
// 8 warps; warp w owns rows (w&3)*32..+32, cols (w>>2)*64..+64.
// ---------------------------------------------------------------------------
__global__ __launch_bounds__(256) void prep_kernel(
    const float* __restrict__ h,
    const float* __restrict__ rel_table,
    const float* __restrict__ time_table,
    const float* __restrict__ W1,
    const float* __restrict__ b1,
    const float* __restrict__ W2,
    const int* __restrict__ qptr,
    int n_nodes, int n_rels, int n_times)
{
    __shared__ __align__(16) __half As[128][136];   // M x K (+pad) ~34.8KB
    __shared__ __align__(16) __half Bs[128][136];   // K x N (+pad) ~34.8KB
    __shared__ float cbias_s[D];
    __shared__ float rq_s[D];

    const int tid  = threadIdx.x;
    const int lane = tid & 31;
    const int w    = tid >> 5;
    const int warp_m = (w & 3) * 32;
    const int warp_n = (w >> 2) * 64;

    const int nb_node = (n_nodes + BM - 1) / BM;
    const int nb_rel  = (n_rels  + BM - 1) / BM;

    if (blockIdx.x == 0 && tid < D)
        g_w2h[tid] = __float2half(__ldg(W2 + tid));
    if (tid < D) cbias_s[tid] = 0.f;

    const float* A;
    __half* C;
    int w_off, M, m0;
    bool is_rel = false;

    int bx = blockIdx.x;
    if (bx < nb_node) {
        A = h; C = g_node_proj; w_off = 0; M = n_nodes; m0 = bx * BM;
    } else if (bx < nb_node + nb_rel) {
        A = rel_table; C = g_rel_proj; w_off = 128; M = n_rels;
        m0 = (bx - nb_node) * BM; is_rel = true;
    } else {
        A = time_table; C = g_time_proj; w_off = 384; M = n_times;
        m0 = (bx - nb_node - nb_rel) * BM;
    }

    if (is_rel && tid < D) {
        int q = qptr[0];
        rq_s[tid] = __ldg(rel_table + (size_t)q * D + tid);
    }

    float acc[2][8][4];
#pragma unroll
    for (int mi = 0; mi < 2; mi++)
#pragma unroll
        for (int ni = 0; ni < 8; ni++)
#pragma unroll
            for (int c = 0; c < 4; c++) acc[mi][ni][c] = 0.f;

    // A tile: 128 x 128, fp32 -> fp16. 4096 float4 sources, 16 per thread.
#pragma unroll
    for (int it = 0; it < 16; it++) {
        int i   = tid + it * 256;
        int row = i >> 5;                   // 32 float4 per row
        int c4  = i & 31;
        float4 v = make_float4(0.f, 0.f, 0.f, 0.f);
        int grow = m0 + row;
        if (grow < M)
            v = *(const float4*)(A + (size_t)grow * D + c4 * 4);
        __half2 h01 = __floats2half2_rn(v.x, v.y);
        __half2 h23 = __floats2half2_rn(v.z, v.w);
        uint2 pv;
        pv.x = *(unsigned*)&h01; pv.y = *(unsigned*)&h23;
        *(uint2*)(&As[row][c4 * 4]) = pv;
    }
    // B tile: 128 x 128, fp32 -> fp16. 4096 float4 sources.
#pragma unroll
    for (int it = 0; it < 16; it++) {
        int i   = tid + it * 256;
        int kk  = i >> 5;
        int c4  = i & 31;
        float4 v = *(const float4*)(W1 + (size_t)(w_off + kk) * D + c4 * 4);
        __half2 h01 = __floats2half2_rn(v.x, v.y);
        __half2 h23 = __floats2half2_rn(v.z, v.w);
        uint2 pv;
        pv.x = *(unsigned*)&h01; pv.y = *(unsigned*)&h23;
        *(uint2*)(&Bs[kk][c4 * 4]) = pv;
    }
    __syncthreads();

#pragma unroll
    for (int ks = 0; ks < 8; ks++) {        // K = 8 x 16
        unsigned a[2][4];
        {
            int arow = (lane & 7) + ((lane >> 3) & 1) * 8;
            int acol = ks * 16 + (lane >> 4) * 8;
#pragma unroll
            for (int mi = 0; mi < 2; mi++)
                ldm_x4(a[mi], smem_u32(&As[warp_m + mi * 16 + arow][acol]));
        }
        unsigned b[8][2];
        {
            int krow = ks * 16 + (lane & 7) + ((lane >> 3) & 1) * 8;
#pragma unroll
            for (int p = 0; p < 4; p++) {
                unsigned r[4];
                int ncol = warp_n + p * 16 + (lane >> 4) * 8;
                ldm_x4_trans(r, smem_u32(&Bs[krow][ncol]));
                b[2 * p][0]     = r[0]; b[2 * p][1]     = r[1];
                b[2 * p + 1][0] = r[2]; b[2 * p + 1][1] = r[3];
            }
        }
#pragma unroll
        for (int mi = 0; mi < 2; mi++)
#pragma unroll
            for (int ni = 0; ni < 8; ni++)
                mma_16816(acc[mi][ni], a[mi], b[ni]);
    }

    if (is_rel) {
        if (tid < D) {
            int j = tid;
            float s = __ldg(b1 + j);
            const float* Wc = W1 + (size_t)256 * D + j;
#pragma unroll 8
            for (int k = 0; k < D; k++)
                s += rq_s[k] * __ldg(Wc + (size_t)k * D);
            cbias_s[j] = s;
        }
        __syncthreads();
    }

    const int erow = lane >> 2;
    const int ecol = (lane & 3) * 2;
#pragma unroll
    for (int mi = 0; mi < 2; mi++) {
#pragma unroll
        for (int ni = 0; ni < 8; ni++) {
            int col = warp_n + ni * 8 + ecol;
            float cb0 = cbias_s[col], cb1 = cbias_s[col + 1];
            int r0 = m0 + warp_m + mi * 16 + erow;
            if (r0 < M) {
                __half2 v = __floats2half2_rn(acc[mi][ni][0] + cb0,
                                              acc[mi][ni][1] + cb1);
                *(__half2*)(C + (size_t)r0 * D + col) = v;
            }
            int r1 = r0 + 8;
            if (r1 < M) {
                __half2 v = __floats2half2_rn(acc[mi][ni][2] + cb0,
                                              acc[mi][ni][3] + cb1);
                *(__half2*)(C + (size_t)r1 * D + col) = v;
            }
        }
    }
}

// ---------------------------------------------------------------------------
// Edge pass (exact R11 form — best measured at 51.4us): 8 lanes/edge,
// lane l covers uint4 slots {l, l+8}; 2 edges (one int2 pair) per iteration;
// index loads prefetched one iteration ahead.
// ---------------------------------------------------------------------------
__device__ __forceinline__ float edge_partial(uint4 av, uint4 bv, uint4 cv,
                                              uint4 wv)
{
    const __half2 z2 = __float2half2_rn(0.f);
    __half2 acc;
    {
        __half2 x = __hmax2(__hadd2(__hadd2(*(__half2*)&av.x, *(__half2*)&bv.x),
                                    *(__half2*)&cv.x), z2);
        acc = __hmul2(x, *(__half2*)&wv.x);
    }
    {
        __half2 x = __hmax2(__hadd2(__hadd2(*(__half2*)&av.y, *(__half2*)&bv.y),
                                    *(__half2*)&cv.y), z2);
        acc = __hfma2(x, *(__half2*)&wv.y, acc);
    }
    {
        __half2 x = __hmax2(__hadd2(__hadd2(*(__half2*)&av.z, *(__half2*)&bv.z),
                                    *(__half2*)&cv.z), z2);
        acc = __hfma2(x, *(__half2*)&wv.z, acc);
    }
    {
        __half2 x = __hmax2(__hadd2(__hadd2(*(__half2*)&av.w, *(__half2*)&bv.w),
                                    *(__half2*)&cv.w), z2);
        acc = __hfma2(x, *(__half2*)&wv.w, acc);
    }
    float2 f = __half22float2(acc);
    return f.x + f.y;
}

__global__ __launch_bounds__(256, 5) void edge_kernel(
    const int* __restrict__ edge_src,
    const int* __restrict__ edge_type,
    const int* __restrict__ edge_time,
    const float* __restrict__ b2,
    float* __restrict__ out, int E)
{
    __shared__ __align__(16) uint4 w2_s[16];

    const int l = threadIdx.x & 7;                          // lane in 8-group
    const int group  = (int)((blockIdx.x * 256u + threadIdx.x) >> 3);
    const int ngroup = (int)(gridDim.x * 256u / 8u);

    if (threadIdx.x < 16)
        w2_s[threadIdx.x] = ((const uint4*)g_w2h)[threadIdx.x];
    __syncthreads();

    const uint4* __restrict__ np = (const uint4*)g_node_proj;
    const uint4* __restrict__ rp = (const uint4*)g_rel_proj;
    const uint4* __restrict__ tp = (const uint4*)g_time_proj;

    const float b2v = __ldg(b2);
    const uint4 wv0 = w2_s[l];
    const uint4 wv1 = w2_s[l + 8];

    const int npair = E >> 1;

    // Prologue: prefetch first iteration's indices.
    int p = group;
    int2 s, r, t;
    if (p < npair) {
        s = __ldg((const int2*)edge_src  + p);
        r = __ldg((const int2*)edge_type + p);
        t = __ldg((const int2*)edge_time + p);
    }

    while (p < npair) {
        const int pn = p + ngroup;
        int2 sn, rn, tn;
        if (pn < npair) {                       // prefetch next iteration
            sn = __ldg((const int2*)edge_src  + pn);
            rn = __ldg((const int2*)edge_type + pn);
            tn = __ldg((const int2*)edge_time + pn);
        }

        // Block-strided slots: l (line 0) and l+8 (line 1).
        size_t o0 = (size_t)l;
        size_t o1 = (size_t)l + 8;
        uint4 avA0 = np[(size_t)s.x * 16 + o0], avA1 = np[(size_t)s.x * 16 + o1];
        uint4 bvA0 = rp[(size_t)r.x * 16 + o0], bvA1 = rp[(size_t)r.x * 16 + o1];
        uint4 cvA0 = tp[(size_t)t.x * 16 + o0], cvA1 = tp[(size_t)t.x * 16 + o1];
        uint4 avB0 = np[(size_t)s.y * 16 + o0], avB1 = np[(size_t)s.y * 16 + o1];
        uint4 bvB0 = rp[(size_t)r.y * 16 + o0], bvB1 = rp[(size_t)r.y * 16 + o1];
        uint4 cvB0 = tp[(size_t)t.y * 16 + o0], cvB1 = tp[(size_t)t.y * 16 + o1];

        float dA = edge_partial(avA0, bvA0, cvA0, wv0)
                 + edge_partial(avA1, bvA1, cvA1, wv1);
        float dB = edge_partial(avB0, bvB0, cvB0, wv0)
                 + edge_partial(avB1, bvB1, cvB1, wv1);

#pragma unroll
        for (int off = 4; off; off >>= 1) {
            dA += __shfl_xor_sync(0xffffffffu, dA, off);
            dB += __shfl_xor_sync(0xffffffffu, dB, off);
        }

        if (l == 0) {
            out[p * 2]     = 1.f / (1.f + __expf(-(dA + b2v)));
            out[p * 2 + 1] = 1.f / (1.f + __expf(-(dB + b2v)));
        }

        p = pn; s = sn; r = rn; t = tn;
    }

    // Odd tail edge handled by group 0.
    if ((E & 1) && group == 0) {
        int e = E - 1;
        int se = __ldg(edge_src + e);
        int re = __ldg(edge_type + e);
        int te = __ldg(edge_time + e);
        size_t o0 = (size_t)l;
        size_t o1 = (size_t)l + 8;
        float d = edge_partial(np[(size_t)se * 16 + o0], rp[(size_t)re * 16 + o0],
                               tp[(size_t)te * 16 + o0], wv0)
                + edge_partial(np[(size_t)se * 16 + o1], rp[(size_t)re * 16 + o1],
                               tp[(size_t)te * 16 + o1], wv1);
#pragma unroll
        for (int off = 4; off; off >>= 1)
            d += __shfl_xor_sync(0xffffffffu, d, off);
        if (l == 0)
            out[e] = 1.f / (1.f + __expf(-(d + b2v)));
    }
}

// ---------------------------------------------------------------------------
extern "C" void kernel_launch(void* const* d_in, const int* in_sizes, int n_in,
                              void* d_out, int out_size)
{
    const float* h          = (const float*)d_in[0];
    const int*   edge_index = (const int*)d_in[1];
    const int*   edge_type  = (const int*)d_in[2];
    const int*   edge_time  = (const int*)d_in[3];
    const int*   query_rel  = (const int*)d_in[4];
    const float* rel_table  = (const float*)d_in[5];
    const float* time_table = (const float*)d_in[6];
    const float* W1         = (const float*)d_in[7];
    const float* b1         = (const float*)d_in[8];
    const float* W2         = (const float*)d_in[9];
    const float* b2         = (const float*)d_in[10];
    float*       out        = (float*)d_out;

    const int n_nodes = in_sizes[0] / D;
    const int n_rels  = in_sizes[5] / D;
    const int n_times = in_sizes[6] / D;
    const int E       = in_sizes[2];

    const int nb_node = (n_nodes + BM - 1) / BM;
    const int nb_rel  = (n_rels  + BM - 1) / BM;
    const int nb_time = (n_times + BM - 1) / BM;

    prep_kernel<<<nb_node + nb_rel + nb_time, 256>>>(
        h, rel_table, time_table, W1, b1, W2, query_rel,
        n_nodes, n_rels, n_times);

    edge_kernel<<<2048, 256>>>(edge_index, edge_type, edge_time, b2, out, E);
}

// round 17
// speedup vs baseline: 1.3974x; 1.0491x over previous
#include <cuda_runtime.h>
#include <cuda_fp16.h>
#include <math.h>

// ---------------------------------------------------------------------------
// out[e] = sigmoid( relu(x_e @ W1 + b1) @ W2 + b2 ),
// x_e = [h[src], rel_table[type], rel_table[q], time_table[time]]
//
// Decomposed into per-node / per-rel / per-time 128x128 projections (fp16),
// computed with HMMA tensor cores in ONE K=128 chunk. Query projection + b1
// folded into rel rows. Edge pass: R11/R16 form, launched as exactly ONE
// persistent wave (740 blocks = 148 SM x 5 blocks) to kill wave-quantization
// tail.
// ---------------------------------------------------------------------------

#define D 128
#define MAX_NODES 100000
#define MAX_RELS  500
#define MAX_TIMES 1000

__device__ __align__(128) __half g_node_proj[(size_t)MAX_NODES * D];
__device__ __align__(128) __half g_rel_proj[(size_t)MAX_RELS * D];   // + rq@W1c + b1
__device__ __align__(128) __half g_time_proj[(size_t)MAX_TIMES * D];
__device__ __align__(16)  __half g_w2h[D];

// ---- mma / ldmatrix helpers ------------------------------------------------
__device__ __forceinline__ unsigned smem_u32(const void* p) {
    return (unsigned)__cvta_generic_to_shared(p);
}
__device__ __forceinline__ void ldm_x4(unsigned* r, unsigned addr) {
    asm volatile("ldmatrix.sync.aligned.m8n8.x4.shared.b16 {%0,%1,%2,%3}, [%4];"
                 : "=r"(r[0]), "=r"(r[1]), "=r"(r[2]), "=r"(r[3]) : "r"(addr));
}
__device__ __forceinline__ void ldm_x4_trans(unsigned* r, unsigned addr) {
    asm volatile("ldmatrix.sync.aligned.m8n8.x4.trans.shared.b16 {%0,%1,%2,%3}, [%4];"
                 : "=r"(r[0]), "=r"(r[1]), "=r"(r[2]), "=r"(r[3]) : "r"(addr));
}
__device__ __forceinline__ void mma_16816(float* c, const unsigned* a,
                                          const unsigned* b) {
    asm volatile(
        "mma.sync.aligned.m16n8k16.row.col.f32.f16.f16.f32 "
        "{%0,%1,%2,%3}, {%4,%5,%6,%7}, {%8,%9}, {%0,%1,%2,%3};"
        : "+f"(c[0]), "+f"(c[1]), "+f"(c[2]), "+f"(c[3])
        : "r"(a[0]), "r"(a[1]), "r"(a[2]), "r"(a[3]), "r"(b[0]), "r"(b[1]));
}

#define BM 128

// ---------------------------------------------------------------------------
// Fused prep kernel (R16 form): 128x128 output tile per block, K=128 in ONE
// chunk. 8 warps; warp w owns rows (w&3)*32..+32, cols (w>>2)*64..+64.
// ---------------------------------------------------------------------------
__global__ __launch_bounds__(256) void prep_kernel(
    const float* __restrict__ h,
    const float* __restrict__ rel_table,
    const float* __restrict__ time_table,
    const float* __restrict__ W1,
    const float* __restrict__ b1,
    const float* __restrict__ W2,
    const int* __restrict__ qptr,
    int n_nodes, int n_rels, int n_times)
{
    __shared__ __align__(16) __half As[128][136];   // M x K (+pad)
    __shared__ __align__(16) __half Bs[128][136];   // K x N (+pad)
    __shared__ float cbias_s[D];
    __shared__ float rq_s[D];

    const int tid  = threadIdx.x;
    const int lane = tid & 31;
    const int w    = tid >> 5;
    const int warp_m = (w & 3) * 32;
    const int warp_n = (w >> 2) * 64;

    const int nb_node = (n_nodes + BM - 1) / BM;
    const int nb_rel  = (n_rels  + BM - 1) / BM;

    if (blockIdx.x == 0 && tid < D)
        g_w2h[tid] = __float2half(__ldg(W2 + tid));
    if (tid < D) cbias_s[tid] = 0.f;

    const float* A;
    __half* C;
    int w_off, M, m0;
    bool is_rel = false;

    int bx = blockIdx.x;
    if (bx < nb_node) {
        A = h; C = g_node_proj; w_off = 0; M = n_nodes; m0 = bx * BM;
    } else if (bx < nb_node + nb_rel) {
        A = rel_table; C = g_rel_proj; w_off = 128; M = n_rels;
        m0 = (bx - nb_node) * BM; is_rel = true;
    } else {
        A = time_table; C = g_time_proj; w_off = 384; M = n_times;
        m0 = (bx - nb_node - nb_rel) * BM;
    }

    if (is_rel && tid < D) {
        int q = qptr[0];
        rq_s[tid] = __ldg(rel_table + (size_t)q * D + tid);
    }

    float acc[2][8][4];
#pragma unroll
    for (int mi = 0; mi < 2; mi++)
#pragma unroll
        for (int ni = 0; ni < 8; ni++)
#pragma unroll
            for (int c = 0; c < 4; c++) acc[mi][ni][c] = 0.f;

    // A tile: 128 x 128, fp32 -> fp16. 16 float4 per thread, all in flight.
#pragma unroll
    for (int it = 0; it < 16; it++) {
        int i   = tid + it * 256;
        int row = i >> 5;                   // 32 float4 per row
        int c4  = i & 31;
        float4 v = make_float4(0.f, 0.f, 0.f, 0.f);
        int grow = m0 + row;
        if (grow < M)
            v = *(const float4*)(A + (size_t)grow * D + c4 * 4);
        __half2 h01 = __floats2half2_rn(v.x, v.y);
        __half2 h23 = __floats2half2_rn(v.z, v.w);
        uint2 pv;
        pv.x = *(unsigned*)&h01; pv.y = *(unsigned*)&h23;
        *(uint2*)(&As[row][c4 * 4]) = pv;
    }
    // B tile: 128 x 128, fp32 -> fp16.
#pragma unroll
    for (int it = 0; it < 16; it++) {
        int i   = tid + it * 256;
        int kk  = i >> 5;
        int c4  = i & 31;
        float4 v = *(const float4*)(W1 + (size_t)(w_off + kk) * D + c4 * 4);
        __half2 h01 = __floats2half2_rn(v.x, v.y);
        __half2 h23 = __floats2half2_rn(v.z, v.w);
        uint2 pv;
        pv.x = *(unsigned*)&h01; pv.y = *(unsigned*)&h23;
        *(uint2*)(&Bs[kk][c4 * 4]) = pv;
    }
    __syncthreads();

#pragma unroll
    for (int ks = 0; ks < 8; ks++) {        // K = 8 x 16
        unsigned a[2][4];
        {
            int arow = (lane & 7) + ((lane >> 3) & 1) * 8;
            int acol = ks * 16 + (lane >> 4) * 8;
#pragma unroll
            for (int mi = 0; mi < 2; mi++)
                ldm_x4(a[mi], smem_u32(&As[warp_m + mi * 16 + arow][acol]));
        }
        unsigned b[8][2];
        {
            int krow = ks * 16 + (lane & 7) + ((lane >> 3) & 1) * 8;
#pragma unroll
            for (int p = 0; p < 4; p++) {
                unsigned r[4];
                int ncol = warp_n + p * 16 + (lane >> 4) * 8;
                ldm_x4_trans(r, smem_u32(&Bs[krow][ncol]));
                b[2 * p][0]     = r[0]; b[2 * p][1]     = r[1];
                b[2 * p + 1][0] = r[2]; b[2 * p + 1][1] = r[3];
            }
        }
#pragma unroll
        for (int mi = 0; mi < 2; mi++)
#pragma unroll
            for (int ni = 0; ni < 8; ni++)
                mma_16816(acc[mi][ni], a[mi], b[ni]);
    }

    if (is_rel) {
        if (tid < D) {
            int j = tid;
            float s = __ldg(b1 + j);
            const float* Wc = W1 + (size_t)256 * D + j;
#pragma unroll 8
            for (int k = 0; k < D; k++)
                s += rq_s[k] * __ldg(Wc + (size_t)k * D);
            cbias_s[j] = s;
        }
        __syncthreads();
    }

    const int erow = lane >> 2;
    const int ecol = (lane & 3) * 2;
#pragma unroll
    for (int mi = 0; mi < 2; mi++) {
#pragma unroll
        for (int ni = 0; ni < 8; ni++) {
            int col = warp_n + ni * 8 + ecol;
            float cb0 = cbias_s[col], cb1 = cbias_s[col + 1];
            int r0 = m0 + warp_m + mi * 16 + erow;
            if (r0 < M) {
                __half2 v = __floats2half2_rn(acc[mi][ni][0] + cb0,
                                              acc[mi][ni][1] + cb1);
                *(__half2*)(C + (size_t)r0 * D + col) = v;
            }
            int r1 = r0 + 8;
            if (r1 < M) {
                __half2 v = __floats2half2_rn(acc[mi][ni][2] + cb0,
                                              acc[mi][ni][3] + cb1);
                *(__half2*)(C + (size_t)r1 * D + col) = v;
            }
        }
    }
}

// ---------------------------------------------------------------------------
// Edge pass (R11/R16 form, single persistent wave): 8 lanes/edge, lane l
// covers uint4 slots {l, l+8}; 2 edges per iteration; index loads prefetched
// one iteration ahead.
// ---------------------------------------------------------------------------
__device__ __forceinline__ float edge_partial(uint4 av, uint4 bv, uint4 cv,
                                              uint4 wv)
{
    const __half2 z2 = __float2half2_rn(0.f);
    __half2 acc;
    {
        __half2 x = __hmax2(__hadd2(__hadd2(*(__half2*)&av.x, *(__half2*)&bv.x),
                                    *(__half2*)&cv.x), z2);
        acc = __hmul2(x, *(__half2*)&wv.x);
    }
    {
        __half2 x = __hmax2(__hadd2(__hadd2(*(__half2*)&av.y, *(__half2*)&bv.y),
                                    *(__half2*)&cv.y), z2);
        acc = __hfma2(x, *(__half2*)&wv.y, acc);
    }
    {
        __half2 x = __hmax2(__hadd2(__hadd2(*(__half2*)&av.z, *(__half2*)&bv.z),
                                    *(__half2*)&cv.z), z2);
        acc = __hfma2(x, *(__half2*)&wv.z, acc);
    }
    {
        __half2 x = __hmax2(__hadd2(__hadd2(*(__half2*)&av.w, *(__half2*)&bv.w),
                                    *(__half2*)&cv.w), z2);
        acc = __hfma2(x, *(__half2*)&wv.w, acc);
    }
    float2 f = __half22float2(acc);
    return f.x + f.y;
}

__global__ __launch_bounds__(256, 5) void edge_kernel(
    const int* __restrict__ edge_src,
    const int* __restrict__ edge_type,
    const int* __restrict__ edge_time,
    const float* __restrict__ b2,
    float* __restrict__ out, int E)
{
    __shared__ __align__(16) uint4 w2_s[16];

    const int l = threadIdx.x & 7;                          // lane in 8-group
    const int group  = (int)((blockIdx.x * 256u + threadIdx.x) >> 3);
    const int ngroup = (int)(gridDim.x * 256u / 8u);

    if (threadIdx.x < 16)
        w2_s[threadIdx.x] = ((const uint4*)g_w2h)[threadIdx.x];
    __syncthreads();

    const uint4* __restrict__ np = (const uint4*)g_node_proj;
    const uint4* __restrict__ rp = (const uint4*)g_rel_proj;
    const uint4* __restrict__ tp = (const uint4*)g_time_proj;

    const float b2v = __ldg(b2);
    const uint4 wv0 = w2_s[l];
    const uint4 wv1 = w2_s[l + 8];

    const int npair = E >> 1;

    // Prologue: prefetch first iteration's indices.
    int p = group;
    int2 s, r, t;
    if (p < npair) {
        s = __ldg((const int2*)edge_src  + p);
        r = __ldg((const int2*)edge_type + p);
        t = __ldg((const int2*)edge_time + p);
    }

    while (p < npair) {
        const int pn = p + ngroup;
        int2 sn, rn, tn;
        if (pn < npair) {                       // prefetch next iteration
            sn = __ldg((const int2*)edge_src  + pn);
            rn = __ldg((const int2*)edge_type + pn);
            tn = __ldg((const int2*)edge_time + pn);
        }

        // Block-strided slots: l (line 0) and l+8 (line 1).
        size_t o0 = (size_t)l;
        size_t o1 = (size_t)l + 8;
        uint4 avA0 = np[(size_t)s.x * 16 + o0], avA1 = np[(size_t)s.x * 16 + o1];
        uint4 bvA0 = rp[(size_t)r.x * 16 + o0], bvA1 = rp[(size_t)r.x * 16 + o1];
        uint4 cvA0 = tp[(size_t)t.x * 16 + o0], cvA1 = tp[(size_t)t.x * 16 + o1];
        uint4 avB0 = np[(size_t)s.y * 16 + o0], avB1 = np[(size_t)s.y * 16 + o1];
        uint4 bvB0 = rp[(size_t)r.y * 16 + o0], bvB1 = rp[(size_t)r.y * 16 + o1];
        uint4 cvB0 = tp[(size_t)t.y * 16 + o0], cvB1 = tp[(size_t)t.y * 16 + o1];

        float dA = edge_partial(avA0, bvA0, cvA0, wv0)
                 + edge_partial(avA1, bvA1, cvA1, wv1);
        float dB = edge_partial(avB0, bvB0, cvB0, wv0)
                 + edge_partial(avB1, bvB1, cvB1, wv1);

#pragma unroll
        for (int off = 4; off; off >>= 1) {
            dA += __shfl_xor_sync(0xffffffffu, dA, off);
            dB += __shfl_xor_sync(0xffffffffu, dB, off);
        }

        if (l == 0) {
            out[p * 2]     = 1.f / (1.f + __expf(-(dA + b2v)));
            out[p * 2 + 1] = 1.f / (1.f + __expf(-(dB + b2v)));
        }

        p = pn; s = sn; r = rn; t = tn;
    }

    // Odd tail edge handled by group 0.
    if ((E & 1) && group == 0) {
        int e = E - 1;
        int se = __ldg(edge_src + e);
        int re = __ldg(edge_type + e);
        int te = __ldg(edge_time + e);
        size_t o0 = (size_t)l;
        size_t o1 = (size_t)l + 8;
        float d = edge_partial(np[(size_t)se * 16 + o0], rp[(size_t)re * 16 + o0],
                               tp[(size_t)te * 16 + o0], wv0)
                + edge_partial(np[(size_t)se * 16 + o1], rp[(size_t)re * 16 + o1],
                               tp[(size_t)te * 16 + o1], wv1);
#pragma unroll
        for (int off = 4; off; off >>= 1)
            d += __shfl_xor_sync(0xffffffffu, d, off);
        if (l == 0)
            out[e] = 1.f / (1.f + __expf(-(d + b2v)));
    }
}

// ---------------------------------------------------------------------------
extern "C" void kernel_launch(void* const* d_in, const int* in_sizes, int n_in,
                              void* d_out, int out_size)
{
    const float* h          = (const float*)d_in[0];
    const int*   edge_index = (const int*)d_in[1];
    const int*   edge_type  = (const int*)d_in[2];
    const int*   edge_time  = (const int*)d_in[3];
    const int*   query_rel  = (const int*)d_in[4];
    const float* rel_table  = (const float*)d_in[5];
    const float* time_table = (const float*)d_in[6];
    const float* W1         = (const float*)d_in[7];
    const float* b1         = (const float*)d_in[8];
    const float* W2         = (const float*)d_in[9];
    const float* b2         = (const float*)d_in[10];
    float*       out        = (float*)d_out;

    const int n_nodes = in_sizes[0] / D;
    const int n_rels  = in_sizes[5] / D;
    const int n_times = in_sizes[6] / D;
    const int E       = in_sizes[2];

    const int nb_node = (n_nodes + BM - 1) / BM;
    const int nb_rel  = (n_rels  + BM - 1) / BM;
    const int nb_time = (n_times + BM - 1) / BM;

    prep_kernel<<<nb_node + nb_rel + nb_time, 256>>>(
        h, rel_table, time_table, W1, b1, W2, query_rel,
        n_nodes, n_rels, n_times);

    // Exactly one persistent wave: 148 SMs x 5 blocks/SM.
    edge_kernel<<<740, 256>>>(edge_index, edge_type, edge_time, b2, out, E);
}